// round 4
// baseline (speedup 1.0000x reference)
#include <cuda_runtime.h>
#include <cuda_bf16.h>

// Problem constants (fixed by setup_inputs)
#define B_    2
#define N_    2048
#define DIM_  1024
#define H_    16
#define HD_   64
#define M_    (B_ * N_)          // 4096 rows
#define SCALE_ 0.125f            // 64^-0.5

// Scratch (allocation guards forbid cudaMalloc; __device__ globals are the
// sanctioned workaround).
__device__ float g_qkv[(size_t)M_ * 3 * DIM_];   // [4096, 3072]
__device__ float g_attn[(size_t)M_ * DIM_];      // [4096, 1024]

// ---------------------------------------------------------------------------
// GEMM: C[M,N] = A[M,K] @ B[N,K]^T (+ bias[N] if non-null)
// 128x128 block tile, BK=16, 256 threads, 8x8 microtile per thread.
// ---------------------------------------------------------------------------
__global__ __launch_bounds__(256) void gemm_nt(
    const float* __restrict__ A, const float* __restrict__ Bm,
    const float* __restrict__ bias, float* __restrict__ C,
    int Md, int Nd, int Kd)
{
    __shared__ float As[16][128];
    __shared__ float Bs[16][128];

    const int tid = threadIdx.x;
    const int tx = tid & 15;        // 0..15 -> column group
    const int ty = tid >> 4;        // 0..15 -> row group
    const int rowBase = blockIdx.y * 128;
    const int colBase = blockIdx.x * 128;

    float acc[8][8];
#pragma unroll
    for (int i = 0; i < 8; i++)
#pragma unroll
        for (int j = 0; j < 8; j++) acc[i][j] = 0.f;

    for (int k0 = 0; k0 < Kd; k0 += 16) {
        // Cooperative load: 128x16 tiles of A and B, stored transposed.
        // f = i*256 + tid covers 512 float4's; r = f>>2 (row), kq = (f&3)*4.
#pragma unroll
        for (int i = 0; i < 2; i++) {
            int f  = i * 256 + tid;
            int r  = f >> 2;
            int kq = (f & 3) * 4;
            float4 va = *(const float4*)(A  + (size_t)(rowBase + r) * Kd + k0 + kq);
            As[kq + 0][r] = va.x; As[kq + 1][r] = va.y;
            As[kq + 2][r] = va.z; As[kq + 3][r] = va.w;
            float4 vb = *(const float4*)(Bm + (size_t)(colBase + r) * Kd + k0 + kq);
            Bs[kq + 0][r] = vb.x; Bs[kq + 1][r] = vb.y;
            Bs[kq + 2][r] = vb.z; Bs[kq + 3][r] = vb.w;
        }
        __syncthreads();

#pragma unroll
        for (int k = 0; k < 16; k++) {
            float a[8], b[8];
            *(float4*)&a[0] = *(const float4*)&As[k][ty * 8];
            *(float4*)&a[4] = *(const float4*)&As[k][ty * 8 + 4];
            *(float4*)&b[0] = *(const float4*)&Bs[k][tx * 8];
            *(float4*)&b[4] = *(const float4*)&Bs[k][tx * 8 + 4];
#pragma unroll
            for (int i = 0; i < 8; i++)
#pragma unroll
                for (int j = 0; j < 8; j++)
                    acc[i][j] += a[i] * b[j];
        }
        __syncthreads();
    }

    // Epilogue
#pragma unroll
    for (int i = 0; i < 8; i++) {
        int r = rowBase + ty * 8 + i;
#pragma unroll
        for (int j = 0; j < 8; j += 4) {
            int c = colBase + tx * 8 + j;
            float4 v;
            v.x = acc[i][j + 0];
            v.y = acc[i][j + 1];
            v.z = acc[i][j + 2];
            v.w = acc[i][j + 3];
            if (bias) {
                v.x += bias[c + 0]; v.y += bias[c + 1];
                v.z += bias[c + 2]; v.w += bias[c + 3];
            }
            *(float4*)(C + (size_t)r * Nd + c) = v;
        }
    }
}

// ---------------------------------------------------------------------------
// Flash-style attention, fp32.
// Grid: (N/64, H, B). 64 threads/block; thread t owns query row mt*64+t.
// q (pre-scaled) and o accumulators live entirely in registers; K/V stream
// through smem in 64-row tiles (row stride 68 floats -> conflict-free STS.128).
// Online softmax processed in 32-key chunks to cap register pressure.
// qkv layout: row (b*N+n) of [*,3072]; q at col h*64, k at 1024+h*64,
// v at 2048+h*64 (matches reshape(B,N,3,H,Dh)).
// ---------------------------------------------------------------------------
__global__ __launch_bounds__(64) void attn_kernel(
    const float* __restrict__ qkv, float* __restrict__ attn_out)
{
    __shared__ float Ks[64][68];
    __shared__ float Vs[64][68];

    const int t  = threadIdx.x;
    const int mt = blockIdx.x;
    const int h  = blockIdx.y;
    const int b  = blockIdx.z;
    const int m  = mt * 64 + t;

    const float* qrow = qkv + (size_t)(b * N_ + m) * (3 * DIM_) + h * HD_;
    float q[64];
#pragma unroll
    for (int d = 0; d < 64; d += 4) {
        float4 v = *(const float4*)(qrow + d);
        q[d + 0] = v.x * SCALE_; q[d + 1] = v.y * SCALE_;
        q[d + 2] = v.z * SCALE_; q[d + 3] = v.w * SCALE_;
    }

    float o[64];
#pragma unroll
    for (int d = 0; d < 64; d++) o[d] = 0.f;
    float mx = -1e30f, l = 0.f;

    for (int kt = 0; kt < N_ / 64; kt++) {
        const float* krow = qkv + (size_t)(b * N_ + kt * 64 + t) * (3 * DIM_)
                            + DIM_ + h * HD_;
        const float* vrow = krow + DIM_;
#pragma unroll
        for (int d = 0; d < 64; d += 4) {
            *(float4*)&Ks[t][d] = *(const float4*)(krow + d);
            *(float4*)&Vs[t][d] = *(const float4*)(vrow + d);
        }
        __syncthreads();

#pragma unroll
        for (int half = 0; half < 2; half++) {
            float s[32];
            float tmax = -1e30f;
#pragma unroll
            for (int j = 0; j < 32; j++) {
                const float* kr = &Ks[half * 32 + j][0];
                float acc = 0.f;
#pragma unroll
                for (int d = 0; d < 64; d += 4) {
                    float4 kk = *(const float4*)(kr + d);
                    acc += q[d + 0] * kk.x + q[d + 1] * kk.y
                         + q[d + 2] * kk.z + q[d + 3] * kk.w;
                }
                s[j] = acc;
                tmax = fmaxf(tmax, acc);
            }
            float mnew = fmaxf(mx, tmax);
            float corr = __expf(mx - mnew);
            l *= corr;
#pragma unroll
            for (int d = 0; d < 64; d++) o[d] *= corr;
#pragma unroll
            for (int j = 0; j < 32; j++) {
                float p = __expf(s[j] - mnew);
                l += p;
                const float* vr = &Vs[half * 32 + j][0];
#pragma unroll
                for (int d = 0; d < 64; d += 4) {
                    float4 vv = *(const float4*)(vr + d);
                    o[d + 0] += p * vv.x; o[d + 1] += p * vv.y;
                    o[d + 2] += p * vv.z; o[d + 3] += p * vv.w;
                }
            }
            mx = mnew;
        }
        __syncthreads();
    }

    const float inv = 1.f / l;
    // Store as [B, N, H, Dh] == transpose(0,2,1,3).reshape(B,N,C)
    float* orow = attn_out + (size_t)(b * N_ + m) * DIM_ + h * HD_;
#pragma unroll
    for (int d = 0; d < 64; d += 4) {
        float4 v;
        v.x = o[d + 0] * inv; v.y = o[d + 1] * inv;
        v.z = o[d + 2] * inv; v.w = o[d + 3] * inv;
        *(float4*)(orow + d) = v;
    }
}

// ---------------------------------------------------------------------------
extern "C" void kernel_launch(void* const* d_in, const int* in_sizes, int n_in,
                              void* d_out, int out_size)
{
    const float* x      = (const float*)d_in[0];   // [2,2048,1024]
    const float* w_qkv  = (const float*)d_in[1];   // [3072,1024]
    const float* w_proj = (const float*)d_in[2];   // [1024,1024]
    const float* b_proj = (const float*)d_in[3];   // [1024]
    float* out = (float*)d_out;                    // [2,2048,1024]

    float *qkv, *attn;
    cudaGetSymbolAddress((void**)&qkv,  g_qkv);
    cudaGetSymbolAddress((void**)&attn, g_attn);

    // 1) QKV projection: [4096,3072] = x @ w_qkv^T
    gemm_nt<<<dim3(3 * DIM_ / 128, M_ / 128), 256>>>(
        x, w_qkv, nullptr, qkv, M_, 3 * DIM_, DIM_);

    // 2) Attention -> [B,N,H,Dh] contiguous = [4096,1024]
    attn_kernel<<<dim3(N_ / 64, H_, B_), 64>>>(qkv, attn);

    // 3) Output projection: out = attn @ w_proj^T + b_proj
    gemm_nt<<<dim3(DIM_ / 128, M_ / 128), 256>>>(
        attn, w_proj, b_proj, out, M_, DIM_, DIM_);
}

// round 5
// speedup vs baseline: 6.0737x; 6.0737x over previous
#include <cuda_runtime.h>
#include <cuda_bf16.h>
#include <cstdint>

// Problem constants
#define B_    2
#define N_    2048
#define DIM_  1024
#define H_    16
#define HD_   64
#define M_    (B_ * N_)          // 4096
#define SCALE_ 0.125f

// Scratch (__device__ globals — allocation guards forbid cudaMalloc)
__device__ float g_qkv[(size_t)M_ * 3 * DIM_];           // [4096, 3072]   50 MB
__device__ float g_attn[(size_t)M_ * DIM_];              // [4096, 1024]   16 MB
__device__ float g_S[(size_t)B_ * H_ * N_ * N_];         // [32, 2048, 2048] 512 MB

// ---------------------------------------------------------------------------
// tf32 helpers
// ---------------------------------------------------------------------------
__device__ __forceinline__ uint32_t f2tf32(float x) {
    uint32_t r;
    asm("cvt.rna.tf32.f32 %0, %1;" : "=r"(r) : "f"(x));
    return r;
}

__device__ __forceinline__ void mma_tf32(float c[4], const uint32_t a[4],
                                         const uint32_t b[2]) {
    asm volatile(
        "mma.sync.aligned.m16n8k8.row.col.f32.tf32.tf32.f32 "
        "{%0,%1,%2,%3}, {%4,%5,%6,%7}, {%8,%9}, {%0,%1,%2,%3};"
        : "+f"(c[0]), "+f"(c[1]), "+f"(c[2]), "+f"(c[3])
        : "r"(a[0]), "r"(a[1]), "r"(a[2]), "r"(a[3]), "r"(b[0]), "r"(b[1]));
}

// ---------------------------------------------------------------------------
// Generic batched tf32 GEMM:  C = scale * (A @ B^T) [+ bias]
//   A: [M,K] row-major (lda), B: [N,K] row-major (ldb) unless TRANSB, in which
//   case B is [K,N] row-major (ldb) and tiles are transposed into smem.
//   Batch offset for grid z: base += (z/zInner)*so + (z%zInner)*si.
// BK = 32. Warp tile WM x WN via m16n8k8 mma.
// ---------------------------------------------------------------------------
template <int BM, int BN, int WM, int WN, bool TRANSB>
__global__ void __launch_bounds__((BM / WM) * (BN / WN) * 32)
gemm_tf32(const float* __restrict__ A, const float* __restrict__ Bm,
          const float* __restrict__ bias, float* __restrict__ C,
          int Kd, int lda, int ldb, int ldc, int zInner,
          long long aso, long long asi, long long bso, long long bsi,
          long long cso, long long csi, float scale)
{
    constexpr int BK  = 32;
    constexpr int BKP = BK + 4;                    // pad -> conflict-free frag reads
    constexpr int NW  = (BM / WM) * (BN / WN);
    constexpr int NT  = NW * 32;

    __shared__ uint32_t As[BM][BKP];
    __shared__ uint32_t Bs[BN][BKP];

    const int z  = blockIdx.z;
    const int zo = z / zInner, zi = z % zInner;
    A  += (size_t)zo * aso + (size_t)zi * asi;
    Bm += (size_t)zo * bso + (size_t)zi * bsi;
    C  += (size_t)zo * cso + (size_t)zi * csi;

    const int tid  = threadIdx.x;
    const int warp = tid >> 5, lane = tid & 31;
    const int g    = lane >> 2, tg = lane & 3;
    const int wm   = (warp % (BM / WM)) * WM;
    const int wn   = (warp / (BM / WM)) * WN;
    const int rowBase = blockIdx.y * BM;
    const int colBase = blockIdx.x * BN;

    float acc[WM / 16][WN / 8][4];
#pragma unroll
    for (int i = 0; i < WM / 16; i++)
#pragma unroll
        for (int j = 0; j < WN / 8; j++)
#pragma unroll
            for (int e = 0; e < 4; e++) acc[i][j][e] = 0.f;

    for (int k0 = 0; k0 < Kd; k0 += BK) {
        // --- load A tile [BM x BK] ---
#pragma unroll
        for (int i = 0; i < BM * BK / (4 * NT); i++) {
            int f  = i * NT + tid;
            int r  = f / (BK / 4);
            int kq = (f % (BK / 4)) * 4;
            float4 v = *(const float4*)(A + (size_t)(rowBase + r) * lda + k0 + kq);
            uint4 u = make_uint4(f2tf32(v.x), f2tf32(v.y), f2tf32(v.z), f2tf32(v.w));
            *(uint4*)&As[r][kq] = u;
        }
        // --- load B tile ---
        if (!TRANSB) {
#pragma unroll
            for (int i = 0; i < BN * BK / (4 * NT); i++) {
                int f  = i * NT + tid;
                int r  = f / (BK / 4);
                int kq = (f % (BK / 4)) * 4;
                float4 v = *(const float4*)(Bm + (size_t)(colBase + r) * ldb + k0 + kq);
                uint4 u = make_uint4(f2tf32(v.x), f2tf32(v.y), f2tf32(v.z), f2tf32(v.w));
                *(uint4*)&Bs[r][kq] = u;
            }
        } else {
            // B is [K,N] row-major; transpose into Bs[n][k]
#pragma unroll
            for (int i = 0; i < BN * BK / (4 * NT); i++) {
                int f  = i * NT + tid;
                int r  = f / (BN / 4);          // k within tile
                int nq = (f % (BN / 4)) * 4;
                float4 v = *(const float4*)(Bm + (size_t)(k0 + r) * ldb + colBase + nq);
                Bs[nq + 0][r] = f2tf32(v.x);
                Bs[nq + 1][r] = f2tf32(v.y);
                Bs[nq + 2][r] = f2tf32(v.z);
                Bs[nq + 3][r] = f2tf32(v.w);
            }
        }
        __syncthreads();

#pragma unroll
        for (int kk = 0; kk < BK; kk += 8) {
            uint32_t af[WM / 16][4];
            uint32_t bf[WN / 8][2];
#pragma unroll
            for (int mt = 0; mt < WM / 16; mt++) {
                int r0 = wm + mt * 16 + g;
                af[mt][0] = As[r0][kk + tg];
                af[mt][1] = As[r0 + 8][kk + tg];
                af[mt][2] = As[r0][kk + tg + 4];
                af[mt][3] = As[r0 + 8][kk + tg + 4];
            }
#pragma unroll
            for (int nt = 0; nt < WN / 8; nt++) {
                int n0 = wn + nt * 8 + g;
                bf[nt][0] = Bs[n0][kk + tg];
                bf[nt][1] = Bs[n0][kk + tg + 4];
            }
#pragma unroll
            for (int mt = 0; mt < WM / 16; mt++)
#pragma unroll
                for (int nt = 0; nt < WN / 8; nt++)
                    mma_tf32(acc[mt][nt], af[mt], bf[nt]);
        }
        __syncthreads();
    }

    // --- epilogue ---
#pragma unroll
    for (int mt = 0; mt < WM / 16; mt++) {
#pragma unroll
        for (int nt = 0; nt < WN / 8; nt++) {
            int r = rowBase + wm + mt * 16 + g;
            int c = colBase + wn + nt * 8 + 2 * tg;
            float2 v0, v1;
            v0.x = acc[mt][nt][0] * scale;
            v0.y = acc[mt][nt][1] * scale;
            v1.x = acc[mt][nt][2] * scale;
            v1.y = acc[mt][nt][3] * scale;
            if (bias) {
                float2 bb = *(const float2*)(bias + c);
                v0.x += bb.x; v0.y += bb.y;
                v1.x += bb.x; v1.y += bb.y;
            }
            *(float2*)(C + (size_t)r * ldc + c)       = v0;
            *(float2*)(C + (size_t)(r + 8) * ldc + c) = v1;
        }
    }
}

// ---------------------------------------------------------------------------
// Row softmax over 2048-wide rows, one block (256 thr) per row, fully
// register-resident (8 elems/thread), one read + one write.
// ---------------------------------------------------------------------------
__global__ __launch_bounds__(256) void softmax2048(float* __restrict__ S)
{
    __shared__ float redM[8];
    __shared__ float redS[8];
    float* row = S + (size_t)blockIdx.x * 2048;
    const int t = threadIdx.x;

    float4 a = ((const float4*)row)[t];
    float4 b = ((const float4*)row)[t + 256];

    float mx = fmaxf(fmaxf(fmaxf(a.x, a.y), fmaxf(a.z, a.w)),
                     fmaxf(fmaxf(b.x, b.y), fmaxf(b.z, b.w)));
#pragma unroll
    for (int o = 16; o; o >>= 1) mx = fmaxf(mx, __shfl_xor_sync(~0u, mx, o));
    if ((t & 31) == 0) redM[t >> 5] = mx;
    __syncthreads();
    mx = redM[0];
#pragma unroll
    for (int i = 1; i < 8; i++) mx = fmaxf(mx, redM[i]);

    a.x = __expf(a.x - mx); a.y = __expf(a.y - mx);
    a.z = __expf(a.z - mx); a.w = __expf(a.w - mx);
    b.x = __expf(b.x - mx); b.y = __expf(b.y - mx);
    b.z = __expf(b.z - mx); b.w = __expf(b.w - mx);

    float s = a.x + a.y + a.z + a.w + b.x + b.y + b.z + b.w;
#pragma unroll
    for (int o = 16; o; o >>= 1) s += __shfl_xor_sync(~0u, s, o);
    if ((t & 31) == 0) redS[t >> 5] = s;
    __syncthreads();
    s = redS[0];
#pragma unroll
    for (int i = 1; i < 8; i++) s += redS[i];
    const float inv = 1.f / s;

    a.x *= inv; a.y *= inv; a.z *= inv; a.w *= inv;
    b.x *= inv; b.y *= inv; b.z *= inv; b.w *= inv;
    ((float4*)row)[t]       = a;
    ((float4*)row)[t + 256] = b;
}

// ---------------------------------------------------------------------------
extern "C" void kernel_launch(void* const* d_in, const int* in_sizes, int n_in,
                              void* d_out, int out_size)
{
    const float* x      = (const float*)d_in[0];   // [2,2048,1024]
    const float* w_qkv  = (const float*)d_in[1];   // [3072,1024]
    const float* w_proj = (const float*)d_in[2];   // [1024,1024]
    const float* b_proj = (const float*)d_in[3];   // [1024]
    float* out = (float*)d_out;                    // [2,2048,1024]

    float *qkv, *attn, *S;
    cudaGetSymbolAddress((void**)&qkv,  g_qkv);
    cudaGetSymbolAddress((void**)&attn, g_attn);
    cudaGetSymbolAddress((void**)&S,    g_S);

    const long long rowsB = (long long)N_ * 3 * DIM_;   // 6291456 (one batch of qkv)
    const long long sBat  = (long long)N_ * N_;          // 4194304 (one S slice)

    // 1) qkv = x @ w_qkv^T   [4096,3072]
    gemm_tf32<128, 128, 64, 32, false><<<dim3(3 * DIM_ / 128, M_ / 128, 1), 256>>>(
        x, w_qkv, nullptr, qkv, DIM_, DIM_, DIM_, 3 * DIM_,
        1, 0, 0, 0, 0, 0, 0, 1.0f);

    // 2) S[z] = scale * Q[z] @ K[z]^T,  z = b*16 + h  -> [32, 2048, 2048]
    gemm_tf32<128, 128, 64, 32, false><<<dim3(N_ / 128, N_ / 128, 32), 256>>>(
        qkv, qkv + DIM_, nullptr, S, HD_, 3 * DIM_, 3 * DIM_, N_,
        H_, rowsB, HD_, rowsB, HD_, 16 * sBat, sBat, SCALE_);

    // 3) row softmax over S
    softmax2048<<<B_ * H_ * N_, 256>>>(S);

    // 4) O[z] = P[z] @ V[z]  (V is [K=2048, N=64] row-major -> TRANSB)
    //    written to [B,N,H,Dh] layout (ldc=1024, head offset h*64)
    gemm_tf32<128, 64, 64, 32, true><<<dim3(1, N_ / 128, 32), 128>>>(
        S, qkv + 2 * DIM_, nullptr, attn, N_, N_, 3 * DIM_, DIM_,
        H_, 16 * sBat, sBat, rowsB, HD_, (long long)N_ * DIM_, HD_, 1.0f);

    // 5) out = attn @ w_proj^T + b_proj
    gemm_tf32<128, 128, 64, 32, false><<<dim3(DIM_ / 128, M_ / 128, 1), 256>>>(
        attn, w_proj, b_proj, out, DIM_, DIM_, DIM_, DIM_,
        1, 0, 0, 0, 0, 0, 0, 1.0f);
}

// round 7
// speedup vs baseline: 7.7814x; 1.2812x over previous
#include <cuda_runtime.h>
#include <cuda_bf16.h>
#include <cstdint>

// Problem constants
#define B_    2
#define N_    2048
#define DIM_  1024
#define H_    16
#define HD_   64
#define M_    (B_ * N_)          // 4096
#define SCALE_ 0.125f

// Scratch (__device__ globals — allocation guards forbid cudaMalloc)
__device__ float g_qkv[(size_t)M_ * 3 * DIM_];           // [4096, 3072]
__device__ float g_attn[(size_t)M_ * DIM_];              // [4096, 1024]

// ---------------------------------------------------------------------------
// tf32 helpers
// ---------------------------------------------------------------------------
__device__ __forceinline__ uint32_t f2tf32(float x) {
    uint32_t r;
    asm("cvt.rna.tf32.f32 %0, %1;" : "=r"(r) : "f"(x));
    return r;
}

__device__ __forceinline__ void mma_tf32(float c[4], const uint32_t a[4],
                                         const uint32_t b0, const uint32_t b1) {
    asm volatile(
        "mma.sync.aligned.m16n8k8.row.col.f32.tf32.tf32.f32 "
        "{%0,%1,%2,%3}, {%4,%5,%6,%7}, {%8,%9}, {%0,%1,%2,%3};"
        : "+f"(c[0]), "+f"(c[1]), "+f"(c[2]), "+f"(c[3])
        : "r"(a[0]), "r"(a[1]), "r"(a[2]), "r"(a[3]), "r"(b0), "r"(b1));
}

// ---------------------------------------------------------------------------
// GEMM (proven in R4): C = A @ B^T (+ bias). BM=BN=128, BK=32, 256 thr.
// ---------------------------------------------------------------------------
__global__ void __launch_bounds__(256)
gemm_tf32(const float* __restrict__ A, const float* __restrict__ Bm,
          const float* __restrict__ bias, float* __restrict__ C,
          int Kd, int lda, int ldb, int ldc)
{
    constexpr int BM = 128, BN = 128, BK = 32, BKP = 36;
    constexpr int WM = 64, WN = 32;

    __shared__ uint32_t As[BM][BKP];
    __shared__ uint32_t Bs[BN][BKP];

    const int tid  = threadIdx.x;
    const int warp = tid >> 5, lane = tid & 31;
    const int g    = lane >> 2, tg = lane & 3;
    const int wm   = (warp % (BM / WM)) * WM;
    const int wn   = (warp / (BM / WM)) * WN;
    const int rowBase = blockIdx.y * BM;
    const int colBase = blockIdx.x * BN;

    float acc[WM / 16][WN / 8][4];
#pragma unroll
    for (int i = 0; i < WM / 16; i++)
#pragma unroll
        for (int j = 0; j < WN / 8; j++)
#pragma unroll
            for (int e = 0; e < 4; e++) acc[i][j][e] = 0.f;

    for (int k0 = 0; k0 < Kd; k0 += BK) {
#pragma unroll
        for (int i = 0; i < 4; i++) {
            int f  = i * 256 + tid;
            int r  = f >> 3;
            int kq = (f & 7) * 4;
            float4 v = *(const float4*)(A + (size_t)(rowBase + r) * lda + k0 + kq);
            *(uint4*)&As[r][kq] =
                make_uint4(f2tf32(v.x), f2tf32(v.y), f2tf32(v.z), f2tf32(v.w));
            float4 w = *(const float4*)(Bm + (size_t)(colBase + r) * ldb + k0 + kq);
            *(uint4*)&Bs[r][kq] =
                make_uint4(f2tf32(w.x), f2tf32(w.y), f2tf32(w.z), f2tf32(w.w));
        }
        __syncthreads();

#pragma unroll
        for (int kk = 0; kk < BK; kk += 8) {
            uint32_t af[WM / 16][4];
#pragma unroll
            for (int mt = 0; mt < WM / 16; mt++) {
                int r0 = wm + mt * 16 + g;
                af[mt][0] = As[r0][kk + tg];
                af[mt][1] = As[r0 + 8][kk + tg];
                af[mt][2] = As[r0][kk + tg + 4];
                af[mt][3] = As[r0 + 8][kk + tg + 4];
            }
#pragma unroll
            for (int nt = 0; nt < WN / 8; nt++) {
                int n0 = wn + nt * 8 + g;
                uint32_t b0 = Bs[n0][kk + tg];
                uint32_t b1 = Bs[n0][kk + tg + 4];
#pragma unroll
                for (int mt = 0; mt < WM / 16; mt++)
                    mma_tf32(acc[mt][nt], af[mt], b0, b1);
            }
        }
        __syncthreads();
    }

#pragma unroll
    for (int mt = 0; mt < WM / 16; mt++) {
#pragma unroll
        for (int nt = 0; nt < WN / 8; nt++) {
            int r = rowBase + wm + mt * 16 + g;
            int c = colBase + wn + nt * 8 + 2 * tg;
            float2 v0 = make_float2(acc[mt][nt][0], acc[mt][nt][1]);
            float2 v1 = make_float2(acc[mt][nt][2], acc[mt][nt][3]);
            if (bias) {
                float2 bb = *(const float2*)(bias + c);
                v0.x += bb.x; v0.y += bb.y;
                v1.x += bb.x; v1.y += bb.y;
            }
            *(float2*)(C + (size_t)r * ldc + c)       = v0;
            *(float2*)(C + (size_t)(r + 8) * ldc + c) = v1;
        }
    }
}

// ---------------------------------------------------------------------------
// Fused flash attention, tf32 tensor cores.
// Grid (N/128, H, B). 256 threads = 8 warps; warp w owns q rows [w*16, w*16+16).
// Per iter: load K/V tile (128 keys) into smem; S = Q@K^T in registers
// (64 f32/lane); online softmax; P -> smem (tf32); O += P@V.
// Smem: Ks[128][68] + Vs[64][132] + Ps[128][132]  = 136192 B (dynamic).
// Ps doubles as the Q-staging buffer during the prologue.
// ---------------------------------------------------------------------------
#define KSTRIDE 68
#define VSTRIDE 132
#define PSTRIDE 132
#define FLASH_SMEM ((128 * KSTRIDE + 64 * VSTRIDE + 128 * PSTRIDE) * 4)

__global__ void __launch_bounds__(256, 1)
flash_attn(const float* __restrict__ qkv, float* __restrict__ attn_out)
{
    extern __shared__ uint32_t sm[];
    uint32_t (*Ks)[KSTRIDE] = (uint32_t(*)[KSTRIDE])sm;
    uint32_t (*Vs)[VSTRIDE] = (uint32_t(*)[VSTRIDE])(sm + 128 * KSTRIDE);
    uint32_t (*Ps)[PSTRIDE] =
        (uint32_t(*)[PSTRIDE])(sm + 128 * KSTRIDE + 64 * VSTRIDE);

    const int tid  = threadIdx.x;
    const int warp = tid >> 5, lane = tid & 31;
    const int g    = lane >> 2, tg = lane & 3;
    const int wm   = warp * 16;
    const int mt   = blockIdx.x;
    const int h    = blockIdx.y;
    const int b    = blockIdx.z;

    const float* base = qkv + (size_t)b * N_ * 3 * DIM_;

    // ---- Prologue: load Q tile (scaled, tf32) via Ps staging, cache frags ----
#pragma unroll
    for (int i = 0; i < 8; i++) {
        int f  = i * 256 + tid;
        int r  = f >> 4;
        int dq = (f & 15) * 4;
        float4 v = *(const float4*)(base + (size_t)(mt * 128 + r) * 3 * DIM_
                                    + h * HD_ + dq);
        Ps[r][dq + 0] = f2tf32(v.x * SCALE_);
        Ps[r][dq + 1] = f2tf32(v.y * SCALE_);
        Ps[r][dq + 2] = f2tf32(v.z * SCALE_);
        Ps[r][dq + 3] = f2tf32(v.w * SCALE_);
    }
    __syncthreads();

    uint32_t qf[8][4];
#pragma unroll
    for (int kk = 0; kk < 8; kk++) {
        qf[kk][0] = Ps[wm + g][kk * 8 + tg];
        qf[kk][1] = Ps[wm + 8 + g][kk * 8 + tg];
        qf[kk][2] = Ps[wm + g][kk * 8 + tg + 4];
        qf[kk][3] = Ps[wm + 8 + g][kk * 8 + tg + 4];
    }
    __syncthreads();   // Ps now reusable

    float o[8][4];
#pragma unroll
    for (int nt = 0; nt < 8; nt++)
#pragma unroll
        for (int e = 0; e < 4; e++) o[nt][e] = 0.f;
    float m0 = -1e30f, m1 = -1e30f, l0 = 0.f, l1 = 0.f;

    // ---- Main loop over key tiles ----
    for (int kt = 0; kt < N_ / 128; kt++) {
        // Load K[128,64] -> Ks[key][d], V[128,64] -> Vs[d][key] (transposed)
#pragma unroll
        for (int i = 0; i < 8; i++) {
            int f  = i * 256 + tid;
            int r  = f >> 4;
            int dq = (f & 15) * 4;
            const float* kp = base + (size_t)(kt * 128 + r) * 3 * DIM_
                              + DIM_ + h * HD_ + dq;
            float4 v = *(const float4*)kp;
            *(uint4*)&Ks[r][dq] =
                make_uint4(f2tf32(v.x), f2tf32(v.y), f2tf32(v.z), f2tf32(v.w));
            float4 w = *(const float4*)(kp + DIM_);
            Vs[dq + 0][r] = f2tf32(w.x);
            Vs[dq + 1][r] = f2tf32(w.y);
            Vs[dq + 2][r] = f2tf32(w.z);
            Vs[dq + 3][r] = f2tf32(w.w);
        }
        __syncthreads();

        // S = Q @ K^T : warp strip [16 x 128]
        float sacc[16][4];
#pragma unroll
        for (int nt = 0; nt < 16; nt++)
#pragma unroll
            for (int e = 0; e < 4; e++) sacc[nt][e] = 0.f;

#pragma unroll
        for (int kk = 0; kk < 8; kk++) {
#pragma unroll
            for (int nt = 0; nt < 16; nt++) {
                uint32_t b0 = Ks[nt * 8 + g][kk * 8 + tg];
                uint32_t b1 = Ks[nt * 8 + g][kk * 8 + tg + 4];
                mma_tf32(sacc[nt], qf[kk], b0, b1);
            }
        }

        // ---- online softmax (rows wm+g and wm+8+g) ----
        float mx0 = -1e30f, mx1 = -1e30f;
#pragma unroll
        for (int nt = 0; nt < 16; nt++) {
            mx0 = fmaxf(mx0, fmaxf(sacc[nt][0], sacc[nt][1]));
            mx1 = fmaxf(mx1, fmaxf(sacc[nt][2], sacc[nt][3]));
        }
        mx0 = fmaxf(mx0, __shfl_xor_sync(~0u, mx0, 1));
        mx0 = fmaxf(mx0, __shfl_xor_sync(~0u, mx0, 2));
        mx1 = fmaxf(mx1, __shfl_xor_sync(~0u, mx1, 1));
        mx1 = fmaxf(mx1, __shfl_xor_sync(~0u, mx1, 2));

        float mn0 = fmaxf(m0, mx0), mn1 = fmaxf(m1, mx1);
        float c0 = __expf(m0 - mn0), c1 = __expf(m1 - mn1);
        l0 *= c0; l1 *= c1;
#pragma unroll
        for (int nt = 0; nt < 8; nt++) {
            o[nt][0] *= c0; o[nt][1] *= c0;
            o[nt][2] *= c1; o[nt][3] *= c1;
        }

        float s0 = 0.f, s1 = 0.f;
#pragma unroll
        for (int nt = 0; nt < 16; nt++) {
            float p0 = __expf(sacc[nt][0] - mn0);
            float p1 = __expf(sacc[nt][1] - mn0);
            float p2 = __expf(sacc[nt][2] - mn1);
            float p3 = __expf(sacc[nt][3] - mn1);
            s0 += p0 + p1; s1 += p2 + p3;
            int c = nt * 8 + 2 * tg;
            uint2 u0 = make_uint2(f2tf32(p0), f2tf32(p1));
            uint2 u1 = make_uint2(f2tf32(p2), f2tf32(p3));
            *(uint2*)&Ps[wm + g][c]     = u0;
            *(uint2*)&Ps[wm + 8 + g][c] = u1;
        }
        s0 += __shfl_xor_sync(~0u, s0, 1);
        s0 += __shfl_xor_sync(~0u, s0, 2);
        s1 += __shfl_xor_sync(~0u, s1, 1);
        s1 += __shfl_xor_sync(~0u, s1, 2);
        l0 += s0; l1 += s1;
        m0 = mn0; m1 = mn1;
        __syncthreads();   // Ps complete (Vs already visible)

        // O += P @ V : [16 x 64] strip, K-dim 128
#pragma unroll
        for (int kk = 0; kk < 16; kk++) {
            uint32_t af[4];
            af[0] = Ps[wm + g][kk * 8 + tg];
            af[1] = Ps[wm + 8 + g][kk * 8 + tg];
            af[2] = Ps[wm + g][kk * 8 + tg + 4];
            af[3] = Ps[wm + 8 + g][kk * 8 + tg + 4];
#pragma unroll
            for (int nt = 0; nt < 8; nt++) {
                uint32_t b0 = Vs[nt * 8 + g][kk * 8 + tg];
                uint32_t b1 = Vs[nt * 8 + g][kk * 8 + tg + 4];
                mma_tf32(o[nt], af, b0, b1);
            }
        }
        __syncthreads();   // protect Ks/Vs/Ps before next tile load
    }

    // ---- Epilogue: normalize and store to [B,N,H,Dh] ----
    const float inv0 = 1.f / l0, inv1 = 1.f / l1;
    float* out0 = attn_out + (size_t)(b * N_ + mt * 128 + wm + g) * DIM_ + h * HD_;
    float* out1 = out0 + (size_t)8 * DIM_;
#pragma unroll
    for (int nt = 0; nt < 8; nt++) {
        int c = nt * 8 + 2 * tg;
        *(float2*)(out0 + c) = make_float2(o[nt][0] * inv0, o[nt][1] * inv0);
        *(float2*)(out1 + c) = make_float2(o[nt][2] * inv1, o[nt][3] * inv1);
    }
}

// ---------------------------------------------------------------------------
extern "C" void kernel_launch(void* const* d_in, const int* in_sizes, int n_in,
                              void* d_out, int out_size)
{
    const float* x      = (const float*)d_in[0];   // [2,2048,1024]
    const float* w_qkv  = (const float*)d_in[1];   // [3072,1024]
    const float* w_proj = (const float*)d_in[2];   // [1024,1024]
    const float* b_proj = (const float*)d_in[3];   // [1024]
    float* out = (float*)d_out;                    // [2,2048,1024]

    float *qkv, *attn;
    cudaGetSymbolAddress((void**)&qkv,  g_qkv);
    cudaGetSymbolAddress((void**)&attn, g_attn);

    static bool attr_done = false;
    if (!attr_done) {
        cudaFuncSetAttribute(flash_attn,
                             cudaFuncAttributeMaxDynamicSharedMemorySize,
                             FLASH_SMEM);
        attr_done = true;
    }

    // 1) qkv = x @ w_qkv^T   [4096,3072]
    gemm_tf32<<<dim3(3 * DIM_ / 128, M_ / 128), 256>>>(
        x, w_qkv, nullptr, qkv, DIM_, DIM_, DIM_, 3 * DIM_);

    // 2) fused attention -> [B,N,H,Dh] = [4096,1024]
    flash_attn<<<dim3(N_ / 128, H_, B_), 256, FLASH_SMEM>>>(qkv, attn);

    // 3) out = attn @ w_proj^T + b_proj
    gemm_tf32<<<dim3(DIM_ / 128, M_ / 128), 256>>>(
        attn, w_proj, b_proj, out, DIM_, DIM_, DIM_, DIM_);
}

// round 9
// speedup vs baseline: 7.8333x; 1.0067x over previous
#include <cuda_runtime.h>
#include <cuda_bf16.h>
#include <cstdint>

// Problem constants
#define B_    2
#define N_    2048
#define DIM_  1024
#define H_    16
#define HD_   64
#define M_    (B_ * N_)          // 4096
#define SCALE_ 0.125f

// Scratch (__device__ globals — allocation guards forbid cudaMalloc)
__device__ float g_qkv[(size_t)M_ * 3 * DIM_];           // [4096, 3072]
__device__ float g_attn[(size_t)M_ * DIM_];              // [4096, 1024]

// ---------------------------------------------------------------------------
// tf32 helpers
// ---------------------------------------------------------------------------
__device__ __forceinline__ uint32_t f2tf32(float x) {
    uint32_t r;
    asm("cvt.rna.tf32.f32 %0, %1;" : "=r"(r) : "f"(x));
    return r;
}

__device__ __forceinline__ void mma_tf32(float c[4], const uint32_t a[4],
                                         const uint32_t b0, const uint32_t b1) {
    asm volatile(
        "mma.sync.aligned.m16n8k8.row.col.f32.tf32.tf32.f32 "
        "{%0,%1,%2,%3}, {%4,%5,%6,%7}, {%8,%9}, {%0,%1,%2,%3};"
        : "+f"(c[0]), "+f"(c[1]), "+f"(c[2]), "+f"(c[3])
        : "r"(a[0]), "r"(a[1]), "r"(a[2]), "r"(a[3]), "r"(b0), "r"(b1));
}

// ---------------------------------------------------------------------------
// Double-buffered tf32 GEMM: C = A @ B^T (+ bias).
// BM=BN=128, BK=32, 256 thr. Per k-tile: issue next LDGs -> mma(buf) ->
// STS(buf^1) -> one syncthreads. LDG latency hidden under mma.
// Dynamic smem: [2][128][36] A + [2][128][36] B = 73728 B.
// ---------------------------------------------------------------------------
#define GEMM_BKP  36
#define GEMM_SMEM (4 * 128 * GEMM_BKP * 4)

__global__ void __launch_bounds__(256, 1)
gemm_tf32(const float* __restrict__ A, const float* __restrict__ Bm,
          const float* __restrict__ bias, float* __restrict__ C,
          int Kd, int lda, int ldb, int ldc)
{
    constexpr int BM = 128, BN = 128, BK = 32, BKP = GEMM_BKP;
    constexpr int WM = 64, WN = 32;

    extern __shared__ uint32_t gsm[];
    uint32_t (*As)[BM][BKP] = (uint32_t(*)[BM][BKP])gsm;
    uint32_t (*Bs)[BN][BKP] = (uint32_t(*)[BN][BKP])(gsm + 2 * BM * BKP);

    const int tid  = threadIdx.x;
    const int warp = tid >> 5, lane = tid & 31;
    const int g    = lane >> 2, tg = lane & 3;
    const int wm   = (warp & 1) * WM;
    const int wn   = (warp >> 1) * WN;
    const int rowBase = blockIdx.y * BM;
    const int colBase = blockIdx.x * BN;

    float acc[WM / 16][WN / 8][4];
#pragma unroll
    for (int i = 0; i < WM / 16; i++)
#pragma unroll
        for (int j = 0; j < WN / 8; j++)
#pragma unroll
            for (int e = 0; e < 4; e++) acc[i][j][e] = 0.f;

    float4 pa[4], pb[4];
    // ---- prologue: load tile 0 ----
#pragma unroll
    for (int i = 0; i < 4; i++) {
        int f  = i * 256 + tid;
        int r  = f >> 3;
        int kq = (f & 7) * 4;
        pa[i] = *(const float4*)(A  + (size_t)(rowBase + r) * lda + kq);
        pb[i] = *(const float4*)(Bm + (size_t)(colBase + r) * ldb + kq);
    }
#pragma unroll
    for (int i = 0; i < 4; i++) {
        int f  = i * 256 + tid;
        int r  = f >> 3;
        int kq = (f & 7) * 4;
        *(uint4*)&As[0][r][kq] =
            make_uint4(f2tf32(pa[i].x), f2tf32(pa[i].y), f2tf32(pa[i].z), f2tf32(pa[i].w));
        *(uint4*)&Bs[0][r][kq] =
            make_uint4(f2tf32(pb[i].x), f2tf32(pb[i].y), f2tf32(pb[i].z), f2tf32(pb[i].w));
    }
    __syncthreads();

    const int nTiles = Kd / BK;
    int buf = 0;
    for (int t = 0; t < nTiles; t++) {
        // issue LDGs for next tile (in flight during mma)
        if (t + 1 < nTiles) {
            int k0 = (t + 1) * BK;
#pragma unroll
            for (int i = 0; i < 4; i++) {
                int f  = i * 256 + tid;
                int r  = f >> 3;
                int kq = (f & 7) * 4;
                pa[i] = *(const float4*)(A  + (size_t)(rowBase + r) * lda + k0 + kq);
                pb[i] = *(const float4*)(Bm + (size_t)(colBase + r) * ldb + k0 + kq);
            }
        }

        // ---- mma over buffer `buf` ----
#pragma unroll
        for (int kk = 0; kk < BK; kk += 8) {
            uint32_t af[WM / 16][4];
#pragma unroll
            for (int mt = 0; mt < WM / 16; mt++) {
                int r0 = wm + mt * 16 + g;
                af[mt][0] = As[buf][r0][kk + tg];
                af[mt][1] = As[buf][r0 + 8][kk + tg];
                af[mt][2] = As[buf][r0][kk + tg + 4];
                af[mt][3] = As[buf][r0 + 8][kk + tg + 4];
            }
#pragma unroll
            for (int nt = 0; nt < WN / 8; nt++) {
                int n0 = wn + nt * 8 + g;
                uint32_t b0 = Bs[buf][n0][kk + tg];
                uint32_t b1 = Bs[buf][n0][kk + tg + 4];
#pragma unroll
                for (int mt = 0; mt < WM / 16; mt++)
                    mma_tf32(acc[mt][nt], af[mt], b0, b1);
            }
        }

        if (t + 1 < nTiles) {
#pragma unroll
            for (int i = 0; i < 4; i++) {
                int f  = i * 256 + tid;
                int r  = f >> 3;
                int kq = (f & 7) * 4;
                *(uint4*)&As[buf ^ 1][r][kq] =
                    make_uint4(f2tf32(pa[i].x), f2tf32(pa[i].y),
                               f2tf32(pa[i].z), f2tf32(pa[i].w));
                *(uint4*)&Bs[buf ^ 1][r][kq] =
                    make_uint4(f2tf32(pb[i].x), f2tf32(pb[i].y),
                               f2tf32(pb[i].z), f2tf32(pb[i].w));
            }
            __syncthreads();
        }
        buf ^= 1;
    }

    // ---- epilogue ----
#pragma unroll
    for (int mt = 0; mt < WM / 16; mt++) {
#pragma unroll
        for (int nt = 0; nt < WN / 8; nt++) {
            int r = rowBase + wm + mt * 16 + g;
            int c = colBase + wn + nt * 8 + 2 * tg;
            float2 v0 = make_float2(acc[mt][nt][0], acc[mt][nt][1]);
            float2 v1 = make_float2(acc[mt][nt][2], acc[mt][nt][3]);
            if (bias) {
                float2 bb = *(const float2*)(bias + c);
                v0.x += bb.x; v0.y += bb.y;
                v1.x += bb.x; v1.y += bb.y;
            }
            *(float2*)(C + (size_t)r * ldc + c)       = v0;
            *(float2*)(C + (size_t)(r + 8) * ldc + c) = v1;
        }
    }
}

// ---------------------------------------------------------------------------
// Fused flash attention, tf32, software-pipelined.
// Grid (N/128, H, B), 256 thr = 8 warps; warp w owns q rows [w*16, w*16+16).
// Per tile: S-mma -> issue next-K LDG -> softmax/P-store -> sync A ->
// issue next-V LDG -> PV-mma -> store K -> sync B -> store V.
// Two syncs per tile; all LDGs overlapped with compute.
// ---------------------------------------------------------------------------
#define KSTRIDE 68
#define VSTRIDE 132
#define PSTRIDE 132
#define FLASH_SMEM ((128 * KSTRIDE + 64 * VSTRIDE + 128 * PSTRIDE) * 4)

__global__ void __launch_bounds__(256, 1)
flash_attn(const float* __restrict__ qkv, float* __restrict__ attn_out)
{
    extern __shared__ uint32_t sm[];
    uint32_t (*Ks)[KSTRIDE] = (uint32_t(*)[KSTRIDE])sm;
    uint32_t (*Vs)[VSTRIDE] = (uint32_t(*)[VSTRIDE])(sm + 128 * KSTRIDE);
    uint32_t (*Ps)[PSTRIDE] =
        (uint32_t(*)[PSTRIDE])(sm + 128 * KSTRIDE + 64 * VSTRIDE);

    const int tid  = threadIdx.x;
    const int warp = tid >> 5, lane = tid & 31;
    const int g    = lane >> 2, tg = lane & 3;
    const int wm   = warp * 16;
    const int mt   = blockIdx.x;
    const int h    = blockIdx.y;
    const int b    = blockIdx.z;

    const float* base = qkv + (size_t)b * N_ * 3 * DIM_;

    // per-thread K/V element coordinates (8 float4 each)
    const int lr = tid >> 4;              // base row helper: f>>4 where f=i*256+tid
    const int ldq = (tid & 15) * 4;       // f&15 constant across i

    // ---- Prologue: Q tile -> Ps staging -> frags ----
#pragma unroll
    for (int i = 0; i < 8; i++) {
        int r = i * 16 + lr;
        float4 v = *(const float4*)(base + (size_t)(mt * 128 + r) * 3 * DIM_
                                    + h * HD_ + ldq);
        Ps[r][ldq + 0] = f2tf32(v.x * SCALE_);
        Ps[r][ldq + 1] = f2tf32(v.y * SCALE_);
        Ps[r][ldq + 2] = f2tf32(v.z * SCALE_);
        Ps[r][ldq + 3] = f2tf32(v.w * SCALE_);
    }
    __syncthreads();

    uint32_t qf[8][4];
#pragma unroll
    for (int kk = 0; kk < 8; kk++) {
        qf[kk][0] = Ps[wm + g][kk * 8 + tg];
        qf[kk][1] = Ps[wm + 8 + g][kk * 8 + tg];
        qf[kk][2] = Ps[wm + g][kk * 8 + tg + 4];
        qf[kk][3] = Ps[wm + 8 + g][kk * 8 + tg + 4];
    }
    __syncthreads();

    // ---- Prologue: K/V tile 0 -> smem ----
#pragma unroll
    for (int i = 0; i < 8; i++) {
        int r = i * 16 + lr;
        const float* kp = base + (size_t)r * 3 * DIM_ + DIM_ + h * HD_ + ldq;
        float4 v = *(const float4*)kp;
        *(uint4*)&Ks[r][ldq] =
            make_uint4(f2tf32(v.x), f2tf32(v.y), f2tf32(v.z), f2tf32(v.w));
        float4 w = *(const float4*)(kp + DIM_);
        Vs[ldq + 0][r] = f2tf32(w.x);
        Vs[ldq + 1][r] = f2tf32(w.y);
        Vs[ldq + 2][r] = f2tf32(w.z);
        Vs[ldq + 3][r] = f2tf32(w.w);
    }
    __syncthreads();

    float o[8][4];
#pragma unroll
    for (int nt = 0; nt < 8; nt++)
#pragma unroll
        for (int e = 0; e < 4; e++) o[nt][e] = 0.f;
    float m0 = -1e30f, m1 = -1e30f, l0 = 0.f, l1 = 0.f;

    constexpr int NT = N_ / 128;
    for (int kt = 0; kt < NT; kt++) {
        const bool more = (kt + 1 < NT);

        // ---- S = Q @ K^T : warp strip [16 x 128] ----
        float sacc[16][4];
#pragma unroll
        for (int nt = 0; nt < 16; nt++)
#pragma unroll
            for (int e = 0; e < 4; e++) sacc[nt][e] = 0.f;
#pragma unroll
        for (int kk = 0; kk < 8; kk++) {
#pragma unroll
            for (int nt = 0; nt < 16; nt++) {
                uint32_t b0 = Ks[nt * 8 + g][kk * 8 + tg];
                uint32_t b1 = Ks[nt * 8 + g][kk * 8 + tg + 4];
                mma_tf32(sacc[nt], qf[kk], b0, b1);
            }
        }

        // issue next-K loads (hidden under softmax)
        float4 pk[8];
        if (more) {
#pragma unroll
            for (int i = 0; i < 8; i++) {
                int r = i * 16 + lr;
                pk[i] = *(const float4*)(base
                        + (size_t)((kt + 1) * 128 + r) * 3 * DIM_
                        + DIM_ + h * HD_ + ldq);
            }
        }

        // ---- online softmax (rows wm+g, wm+8+g) ----
        float mx0 = -1e30f, mx1 = -1e30f;
#pragma unroll
        for (int nt = 0; nt < 16; nt++) {
            mx0 = fmaxf(mx0, fmaxf(sacc[nt][0], sacc[nt][1]));
            mx1 = fmaxf(mx1, fmaxf(sacc[nt][2], sacc[nt][3]));
        }
        mx0 = fmaxf(mx0, __shfl_xor_sync(~0u, mx0, 1));
        mx0 = fmaxf(mx0, __shfl_xor_sync(~0u, mx0, 2));
        mx1 = fmaxf(mx1, __shfl_xor_sync(~0u, mx1, 1));
        mx1 = fmaxf(mx1, __shfl_xor_sync(~0u, mx1, 2));

        float mn0 = fmaxf(m0, mx0), mn1 = fmaxf(m1, mx1);
        float c0 = __expf(m0 - mn0), c1 = __expf(m1 - mn1);
        l0 *= c0; l1 *= c1;
#pragma unroll
        for (int nt = 0; nt < 8; nt++) {
            o[nt][0] *= c0; o[nt][1] *= c0;
            o[nt][2] *= c1; o[nt][3] *= c1;
        }

        float s0 = 0.f, s1 = 0.f;
#pragma unroll
        for (int nt = 0; nt < 16; nt++) {
            float p0 = __expf(sacc[nt][0] - mn0);
            float p1 = __expf(sacc[nt][1] - mn0);
            float p2 = __expf(sacc[nt][2] - mn1);
            float p3 = __expf(sacc[nt][3] - mn1);
            s0 += p0 + p1; s1 += p2 + p3;
            int c = nt * 8 + 2 * tg;
            *(uint2*)&Ps[wm + g][c]     = make_uint2(f2tf32(p0), f2tf32(p1));
            *(uint2*)&Ps[wm + 8 + g][c] = make_uint2(f2tf32(p2), f2tf32(p3));
        }
        s0 += __shfl_xor_sync(~0u, s0, 1);
        s0 += __shfl_xor_sync(~0u, s0, 2);
        s1 += __shfl_xor_sync(~0u, s1, 1);
        s1 += __shfl_xor_sync(~0u, s1, 2);
        l0 += s0; l1 += s1;
        m0 = mn0; m1 = mn1;
        __syncthreads();   // (A) all S-mma done, Ps ready

        // issue next-V loads (hidden under PV-mma)
        float4 pv[8];
        if (more) {
#pragma unroll
            for (int i = 0; i < 8; i++) {
                int r = i * 16 + lr;
                pv[i] = *(const float4*)(base
                        + (size_t)((kt + 1) * 128 + r) * 3 * DIM_
                        + 2 * DIM_ + h * HD_ + ldq);
            }
        }

        // ---- O += P @ V ----
#pragma unroll
        for (int kk = 0; kk < 16; kk++) {
            uint32_t af[4];
            af[0] = Ps[wm + g][kk * 8 + tg];
            af[1] = Ps[wm + 8 + g][kk * 8 + tg];
            af[2] = Ps[wm + g][kk * 8 + tg + 4];
            af[3] = Ps[wm + 8 + g][kk * 8 + tg + 4];
#pragma unroll
            for (int nt = 0; nt < 8; nt++) {
                uint32_t b0 = Vs[nt * 8 + g][kk * 8 + tg];
                uint32_t b1 = Vs[nt * 8 + g][kk * 8 + tg + 4];
                mma_tf32(o[nt], af, b0, b1);
            }
        }

        if (more) {
            // store next K (safe: sync A guarantees all S-mma finished)
#pragma unroll
            for (int i = 0; i < 8; i++) {
                int r = i * 16 + lr;
                *(uint4*)&Ks[r][ldq] =
                    make_uint4(f2tf32(pk[i].x), f2tf32(pk[i].y),
                               f2tf32(pk[i].z), f2tf32(pk[i].w));
            }
        }
        __syncthreads();   // (B) all PV-mma done -> Vs writable
        if (more) {
#pragma unroll
            for (int i = 0; i < 8; i++) {
                int r = i * 16 + lr;
                Vs[ldq + 0][r] = f2tf32(pv[i].x);
                Vs[ldq + 1][r] = f2tf32(pv[i].y);
                Vs[ldq + 2][r] = f2tf32(pv[i].z);
                Vs[ldq + 3][r] = f2tf32(pv[i].w);
            }
        }
    }

    // ---- Epilogue ----
    const float inv0 = 1.f / l0, inv1 = 1.f / l1;
    float* out0 = attn_out + (size_t)(b * N_ + mt * 128 + wm + g) * DIM_ + h * HD_;
    float* out1 = out0 + (size_t)8 * DIM_;
#pragma unroll
    for (int nt = 0; nt < 8; nt++) {
        int c = nt * 8 + 2 * tg;
        *(float2*)(out0 + c) = make_float2(o[nt][0] * inv0, o[nt][1] * inv0);
        *(float2*)(out1 + c) = make_float2(o[nt][2] * inv1, o[nt][3] * inv1);
    }
}

// ---------------------------------------------------------------------------
extern "C" void kernel_launch(void* const* d_in, const int* in_sizes, int n_in,
                              void* d_out, int out_size)
{
    const float* x      = (const float*)d_in[0];   // [2,2048,1024]
    const float* w_qkv  = (const float*)d_in[1];   // [3072,1024]
    const float* w_proj = (const float*)d_in[2];   // [1024,1024]
    const float* b_proj = (const float*)d_in[3];   // [1024]
    float* out = (float*)d_out;                    // [2,2048,1024]

    float *qkv, *attn;
    cudaGetSymbolAddress((void**)&qkv,  g_qkv);
    cudaGetSymbolAddress((void**)&attn, g_attn);

    static bool attr_done = false;
    if (!attr_done) {
        cudaFuncSetAttribute(flash_attn,
                             cudaFuncAttributeMaxDynamicSharedMemorySize,
                             FLASH_SMEM);
        cudaFuncSetAttribute(gemm_tf32,
                             cudaFuncAttributeMaxDynamicSharedMemorySize,
                             GEMM_SMEM);
        attr_done = true;
    }

    // 1) qkv = x @ w_qkv^T   [4096,3072]
    gemm_tf32<<<dim3(3 * DIM_ / 128, M_ / 128), 256, GEMM_SMEM>>>(
        x, w_qkv, nullptr, qkv, DIM_, DIM_, DIM_, 3 * DIM_);

    // 2) fused attention -> [B,N,H,Dh] = [4096,1024]
    flash_attn<<<dim3(N_ / 128, H_, B_), 256, FLASH_SMEM>>>(qkv, attn);

    // 3) out = attn @ w_proj^T + b_proj
    gemm_tf32<<<dim3(DIM_ / 128, M_ / 128), 256, GEMM_SMEM>>>(
        attn, w_proj, b_proj, out, DIM_, DIM_, DIM_, DIM_);
}